// round 10
// baseline (speedup 1.0000x reference)
#include <cuda_runtime.h>
#include <cstdint>

#define N_   8
#define C_   64
#define H_   256
#define W_   256
#define G_   8
#define CPG_ 8               // channels per group
#define ROWS 16              // rows per block strip
#define TR   (ROWS+2)        // tile rows incl. halo = 18
#define CHUNKS (H_/ROWS)     // 16
#define EPS_ 1e-5f
#define NT   256             // 64 col-groups x 4 row-groups
#define W4_  (W_/4)          // 64
#define TQ   (TR*W4_)        // 1152 staging quads
#define WP   264             // padded row width: col3 = L-halo, cols4..259 data, col260 = R-halo
#define BUFF (TR*WP)         // floats per tile buffer (4752)
#define HWQ  (H_*W_/4)
#define CSPLIT 8
#define CHPB (C_/CSPLIT)

typedef unsigned long long u64;

// Static scratch (no runtime allocation)
__device__ float g_part[N_*G_*CHUNKS*2];
__device__ float g_esum[(size_t)N_*G_*H_*W_];      // per-(n,g) sum of exp

// ---- f32x2 packed helpers (sm_100+) ----
__device__ __forceinline__ u64 pack2(float lo, float hi) {
    u64 r; asm("mov.b64 %0,{%1,%2};" : "=l"(r) : "f"(lo), "f"(hi)); return r;
}
__device__ __forceinline__ void unpack2(u64 v, float& lo, float& hi) {
    asm("mov.b64 {%0,%1},%2;" : "=f"(lo), "=f"(hi) : "l"(v));
}
__device__ __forceinline__ u64 fma2(u64 a, u64 b, u64 c) {
    u64 d; asm("fma.rn.f32x2 %0,%1,%2,%3;" : "=l"(d) : "l"(a), "l"(b), "l"(c)); return d;
}
__device__ __forceinline__ u64 add2(u64 a, u64 b) {
    u64 d; asm("add.rn.f32x2 %0,%1,%2;" : "=l"(d) : "l"(a), "l"(b)); return d;
}
__device__ __forceinline__ u64 mul2(u64 a, u64 b) {
    u64 d; asm("mul.rn.f32x2 %0,%1,%2;" : "=l"(d) : "l"(a), "l"(b)); return d;
}
__device__ __forceinline__ float tanh_fast(float x) {
    float y; asm("tanh.approx.f32 %0,%1;" : "=f"(y) : "f"(x)); return y;
}
__device__ __forceinline__ float ex2_fast(float x) {
    float y; asm("ex2.approx.f32 %0,%1;" : "=f"(y) : "f"(x)); return y;
}

#define CP_COMMIT() asm volatile("cp.async.commit_group;")
#define CP_WAIT0()  asm volatile("cp.async.wait_group 0;")

// Stage one (TR x W_) channel tile gmem -> padded smem rows via cp.async.cg.
__device__ __forceinline__ void cpa_tile(unsigned sbase, const float4* __restrict__ xc4,
                                         int h0, int tid) {
    #pragma unroll
    for (int i = 0; i < 5; ++i) {
        const int idx = tid + i*NT;
        if (idx < TQ) {
            const int r = idx >> 6, q = idx & (W4_-1);
            const int h = h0 - 1 + r;
            const bool v = (h >= 0) && (h < H_);
            const float4* src = xc4 + (v ? (h*W4_ + q) : q);
            const int sz = v ? 16 : 0;
            const unsigned dst = sbase + (unsigned)(r*WP + 4 + 4*q)*4u;
            asm volatile("cp.async.cg.shared.global [%0], [%1], 16, %2;"
                         :: "r"(dst), "l"(src), "r"(sz));
        }
    }
}

// 5 shifted operand pairs for one tile row, covering 4 pixels (2 f32x2 pairs)
struct RowP { u64 P0, P1, P2, P3, P4; };

__device__ __forceinline__ RowP load_row(const float* rb) {   // rb -> first data col of this thread
    RowP p;
    const float  L = rb[-1];
    const float4 M = *(const float4*)rb;            // LDS.128, 16B aligned
    const float  R = rb[4];
    p.P0 = pack2(L,   M.x); p.P1 = pack2(M.x, M.y); p.P2 = pack2(M.y, M.z);
    p.P3 = pack2(M.z, M.w); p.P4 = pack2(M.w, R);
    return p;
}

// packed 3x3 conv: pair A = pixels {0,1}, pair B = pixels {2,3}
#define CONV2(r0, r1, r2, wkp, cA, cB)                                              \
    cA = mul2(r0.P0, wkp[0]); cA = fma2(r0.P1, wkp[1], cA); cA = fma2(r0.P2, wkp[2], cA); \
    cA = fma2(r1.P0, wkp[3], cA); cA = fma2(r1.P1, wkp[4], cA); cA = fma2(r1.P2, wkp[5], cA); \
    cA = fma2(r2.P0, wkp[6], cA); cA = fma2(r2.P1, wkp[7], cA); cA = fma2(r2.P2, wkp[8], cA); \
    cB = mul2(r0.P2, wkp[0]); cB = fma2(r0.P3, wkp[1], cB); cB = fma2(r0.P4, wkp[2], cB); \
    cB = fma2(r1.P2, wkp[3], cB); cB = fma2(r1.P3, wkp[4], cB); cB = fma2(r1.P4, wkp[5], cB); \
    cB = fma2(r2.P2, wkp[6], cB); cB = fma2(r2.P3, wkp[7], cB); cB = fma2(r2.P4, wkp[8], cB);

// zero halo columns (cols 3 and 260) of all TR rows in both buffers
#define ZERO_HALOS(bufbase)                                               \
    if (tid < 2*TR*2) {                                                   \
        const int b = tid / (TR*2), rest = tid % (TR*2);                  \
        const int row = rest >> 1, col = (rest & 1) ? 260 : 3;            \
        (bufbase)[b*BUFF + row*WP + col] = 0.f;                           \
    }

// load the 9 x CPG_ weights as duplicated float2
#define LOAD_WEIGHTS()                                                    \
    if (tid >= 128 && tid < 128 + 9*CPG_) {                               \
        const int t = tid - 128;                                          \
        const int j = t / CPG_, cc = t % CPG_;                            \
        const float w = wgt[j*C_ + g*CPG_ + cc];                          \
        wsm2[j][cc] = make_float2(w, w);                                  \
    }

// ---------------- Pass 1: depthwise conv + per-(n,g,chunk) sum / sumsq ----------------
__global__ __launch_bounds__(NT) void k_pass1(const float* __restrict__ x,
                                              const float* __restrict__ wgt) {
    __shared__ __align__(16) float buf[2*BUFF];     // 38 KB double buffer
    __shared__ float2 wsm2[9][CPG_];
    __shared__ float  red[8], red2[8];

    const int bid   = blockIdx.x;
    const int chunk = bid % CHUNKS;
    const int g     = (bid / CHUNKS) % G_;
    const int n     = bid / (CHUNKS * G_);
    const int h0    = chunk * ROWS;
    const int tid   = threadIdx.x;
    const int tx    = tid & 63;                     // cols 4tx..4tx+3
    const int ty    = tid >> 6;                     // rows 4ty..4ty+3
    const int lane  = tid & 31, wid = tid >> 5;

    ZERO_HALOS(buf);
    LOAD_WEIGHTS();

    const unsigned sb0 = (unsigned)__cvta_generic_to_shared(&buf[0]);
    const float4* x4 = (const float4*)x;
    const size_t plane0 = (size_t)(n*C_ + g*CPG_) * HWQ;

    cpa_tile(sb0, x4 + plane0, h0, tid); CP_COMMIT();

    u64 gsP = 0, gs2P = 0;
    int cur = 0;
    for (int cc = 0; cc < CPG_; ++cc) {
        CP_WAIT0();                                 // channel cc resident
        __syncthreads();                            // all warps done reading buf[cur^1]
        if (cc + 1 < CPG_) {
            cpa_tile(sb0 + (unsigned)((cur^1)*BUFF)*4u,
                     x4 + plane0 + (size_t)(cc+1)*HWQ, h0, tid);
            CP_COMMIT();
        }

        u64 wkp[9];
        #pragma unroll
        for (int j = 0; j < 9; ++j) wkp[j] = *(const u64*)&wsm2[j][cc];

        const float* tb = buf + cur*BUFF + 4 + 4*tx;
        RowP r0 = load_row(tb + (4*ty+0)*WP);
        RowP r1 = load_row(tb + (4*ty+1)*WP);
        #pragma unroll
        for (int rr = 0; rr < 4; ++rr) {
            RowP r2 = load_row(tb + (4*ty+2+rr)*WP);
            u64 cA, cB;
            CONV2(r0, r1, r2, wkp, cA, cB);
            gsP  = add2(gsP, add2(cA, cB));
            gs2P = fma2(cA, cA, gs2P);
            gs2P = fma2(cB, cB, gs2P);
            r0 = r1; r1 = r2;
        }
        cur ^= 1;
    }

    float a, b, gs, gs2;
    unpack2(gsP,  a, b); gs  = a + b;
    unpack2(gs2P, a, b); gs2 = a + b;
    #pragma unroll
    for (int off = 16; off; off >>= 1) {
        gs  += __shfl_down_sync(0xffffffffu, gs,  off);
        gs2 += __shfl_down_sync(0xffffffffu, gs2, off);
    }
    if (lane == 0) { red[wid] = gs; red2[wid] = gs2; }
    __syncthreads();
    if (wid == 0) {
        float s  = (lane < 8) ? red[lane]  : 0.f;
        float s2 = (lane < 8) ? red2[lane] : 0.f;
        #pragma unroll
        for (int off = 4; off; off >>= 1) {
            s  += __shfl_down_sync(0xffffffffu, s,  off);
            s2 += __shfl_down_sync(0xffffffffu, s2, off);
        }
        if (lane == 0) {
            const int idx = ((n*G_ + g)*CHUNKS + chunk)*2;
            g_part[idx]   = s;
            g_part[idx+1] = s2;
        }
    }
}

// ---------------- Pass 2a: conv recompute + norm/act/residual + group exp-sum ----------------
__global__ __launch_bounds__(NT) void k_pass2a(const float* __restrict__ x,
                                               const float* __restrict__ wgt) {
    __shared__ __align__(16) float buf[2*BUFF];
    __shared__ float2 wsm2[9][CPG_];
    __shared__ float  s_stats[2];

    const int bid   = (gridDim.x - 1) - blockIdx.x;
    const int chunk = bid % CHUNKS;
    const int g     = (bid / CHUNKS) % G_;
    const int n     = bid / (CHUNKS * G_);
    const int h0    = chunk * ROWS;
    const int tid   = threadIdx.x;
    const int tx    = tid & 63;
    const int ty    = tid >> 6;

    ZERO_HALOS(buf);
    LOAD_WEIGHTS();
    // fold stats reduce: CHUNKS(=16) chunk-partials for this (n,g), warp 7
    if (tid >= 224) {
        const int l = tid - 224;
        const int sg = (n*G_ + g)*CHUNKS;
        float s  = (l < CHUNKS) ? g_part[(sg + l)*2]     : 0.f;
        float s2 = (l < CHUNKS) ? g_part[(sg + l)*2 + 1] : 0.f;
        #pragma unroll
        for (int off = 16; off; off >>= 1) {
            s  += __shfl_down_sync(0xffffffffu, s,  off);
            s2 += __shfl_down_sync(0xffffffffu, s2, off);
        }
        if (l == 0) {
            const float inv = 1.0f / (float)(CPG_*H_*W_);
            const float m = s * inv;
            const float v = s2 * inv - m*m;
            s_stats[0] = m;
            s_stats[1] = rsqrtf(v + EPS_);
        }
    }

    const unsigned sb0 = (unsigned)__cvta_generic_to_shared(&buf[0]);
    const float4* x4 = (const float4*)x;
    const size_t plane0 = (size_t)(n*C_ + g*CPG_) * HWQ;

    cpa_tile(sb0, x4 + plane0, h0, tid); CP_COMMIT();

    u64 acc[8];                                     // 4 rows x {A,B}
    #pragma unroll
    for (int i = 0; i < 8; ++i) acc[i] = 0;

    const u64 threeP = pack2(3.0f, 3.0f);
    const u64 sixthP = pack2(1.0f/6.0f, 1.0f/6.0f);
    const u64 log2eP = pack2(1.4426950408889634f, 1.4426950408889634f);

    int cur = 0;
    for (int cc = 0; cc < CPG_; ++cc) {
        CP_WAIT0();
        __syncthreads();                            // also publishes s_stats
        const float mean = s_stats[0];
        const float rstd = s_stats[1];
        const u64 rstdP = pack2(rstd, rstd);
        const u64 nmrP  = pack2(-mean*rstd, -mean*rstd);
        if (cc + 1 < CPG_) {
            cpa_tile(sb0 + (unsigned)((cur^1)*BUFF)*4u,
                     x4 + plane0 + (size_t)(cc+1)*HWQ, h0, tid);
            CP_COMMIT();
        }

        u64 wkp[9];
        #pragma unroll
        for (int j = 0; j < 9; ++j) wkp[j] = *(const u64*)&wsm2[j][cc];

        const float* tb = buf + cur*BUFF + 4 + 4*tx;
        RowP r0 = load_row(tb + (4*ty+0)*WP);
        RowP r1 = load_row(tb + (4*ty+1)*WP);
        #pragma unroll
        for (int rr = 0; rr < 4; ++rr) {
            RowP r2 = load_row(tb + (4*ty+2+rr)*WP);
            u64 cv[2];
            CONV2(r0, r1, r2, wkp, cv[0], cv[1]);
            #pragma unroll
            for (int h = 0; h < 2; ++h) {
                const u64 vP = fma2(cv[h], rstdP, nmrP);   // (conv-mean)*rstd
                float v0, v1; unpack2(vP, v0, v1);
                const u64 tP = pack2(tanh_fast(v0), tanh_fast(v1));
                // t in (-1,1) => clip(t+3,0,6) == t+3: xr = conv + t*(t+3)/6
                const u64 xrP = fma2(mul2(tP, sixthP), add2(tP, threeP), cv[h]);
                const u64 aP  = mul2(xrP, log2eP);
                float a0, a1; unpack2(aP, a0, a1);
                const u64 eP = pack2(ex2_fast(a0), ex2_fast(a1));
                acc[rr*2+h] = add2(acc[rr*2+h], eP);
            }
            r0 = r1; r1 = r2;
        }
        cur ^= 1;
    }

    float* es = g_esum + ((size_t)(n*G_ + g)*H_ + h0 + 4*ty)*W_ + 4*tx;
    #pragma unroll
    for (int rr = 0; rr < 4; ++rr) {
        float4 o;
        unpack2(acc[rr*2+0], o.x, o.y);
        unpack2(acc[rr*2+1], o.z, o.w);
        *(float4*)(es + rr*W_) = o;
    }
}

// ---------------- Pass 2b: combine groups, log, broadcast 8 channels/block ----------------
__global__ __launch_bounds__(256) void k_pass2b(float* __restrict__ out) {
    const int p   = blockIdx.x * 256 + threadIdx.x;
    const int n   = p >> 14;
    const int pix = p & (HWQ - 1);
    const int c0  = blockIdx.y * CHPB;

    const float4* e4 = (const float4*)g_esum;
    const size_t ebase = (size_t)n*G_*HWQ + pix;
    float4 s = __ldg(&e4[ebase]);
    #pragma unroll
    for (int g = 1; g < G_; ++g) {
        const float4 v = __ldg(&e4[ebase + (size_t)g*HWQ]);
        s.x += v.x; s.y += v.y; s.z += v.z; s.w += v.w;
    }
    float4 L;
    L.x = __logf(s.x); L.y = __logf(s.y); L.z = __logf(s.z); L.w = __logf(s.w);

    float4* o4 = (float4*)out;
    const size_t obase = (size_t)n*C_*HWQ + (size_t)c0*HWQ + pix;
    #pragma unroll
    for (int c = 0; c < CHPB; ++c) __stcs(&o4[obase + (size_t)c*HWQ], L);
}

extern "C" void kernel_launch(void* const* d_in, const int* in_sizes, int n_in,
                              void* d_out, int out_size) {
    const float* x   = (const float*)d_in[0];       // [8,64,256,256]
    const float* wgt = (const float*)d_in[1];       // [3,3,64]
    float* out = (float*)d_out;

    k_pass1 <<<N_*G_*CHUNKS, NT>>>(x, wgt);
    k_pass2a<<<N_*G_*CHUNKS, NT>>>(x, wgt);
    k_pass2b<<<dim3((N_*HWQ)/256, CSPLIT), 256>>>(out);
}

// round 11
// speedup vs baseline: 1.0377x; 1.0377x over previous
#include <cuda_runtime.h>
#include <cstdint>

#define N_   8
#define C_   64
#define H_   256
#define W_   256
#define G_   8
#define CPG_ 8               // channels per group
#define ROWS 8               // rows per block strip
#define TR   (ROWS+2)        // tile rows incl. halo
#define CHUNKS (H_/ROWS)     // 32
#define EPS_ 1e-5f
#define NT   128             // 64 col-groups x 2 row-groups
#define W4_  (W_/4)          // 64
#define TQ   (TR*W4_)        // 640 staging quads (= 5*NT exactly)
#define WP   264             // padded row width: col3 = L-halo, cols4..259 data, col260 = R-halo
#define BUFF (TR*WP)         // floats per tile buffer
#define HWQ  (H_*W_/4)
#define CSPLIT 8
#define CHPB (C_/CSPLIT)

typedef unsigned long long u64;

// Static scratch (no runtime allocation)
__device__ float g_part[N_*G_*CHUNKS*2];
__device__ float g_esum[(size_t)N_*G_*H_*W_];      // per-(n,g) sum of exp

// ---- f32x2 packed helpers (sm_100+) ----
__device__ __forceinline__ u64 pack2(float lo, float hi) {
    u64 r; asm("mov.b64 %0,{%1,%2};" : "=l"(r) : "f"(lo), "f"(hi)); return r;
}
__device__ __forceinline__ void unpack2(u64 v, float& lo, float& hi) {
    asm("mov.b64 {%0,%1},%2;" : "=f"(lo), "=f"(hi) : "l"(v));
}
__device__ __forceinline__ u64 fma2(u64 a, u64 b, u64 c) {
    u64 d; asm("fma.rn.f32x2 %0,%1,%2,%3;" : "=l"(d) : "l"(a), "l"(b), "l"(c)); return d;
}
__device__ __forceinline__ u64 add2(u64 a, u64 b) {
    u64 d; asm("add.rn.f32x2 %0,%1,%2;" : "=l"(d) : "l"(a), "l"(b)); return d;
}
__device__ __forceinline__ u64 mul2(u64 a, u64 b) {
    u64 d; asm("mul.rn.f32x2 %0,%1,%2;" : "=l"(d) : "l"(a), "l"(b)); return d;
}
__device__ __forceinline__ float tanh_fast(float x) {
    float y; asm("tanh.approx.f32 %0,%1;" : "=f"(y) : "f"(x)); return y;
}
__device__ __forceinline__ float ex2_fast(float x) {
    float y; asm("ex2.approx.f32 %0,%1;" : "=f"(y) : "f"(x)); return y;
}

#define CP_COMMIT() asm volatile("cp.async.commit_group;")
#define CP_WAIT1()  asm volatile("cp.async.wait_group 1;")

// Stage one (TR x W_) channel tile gmem -> padded smem rows via cp.async.cg.
__device__ __forceinline__ void cpa_tile(unsigned sbase, const float4* __restrict__ xc4,
                                         int h0, int tid) {
    #pragma unroll
    for (int i = 0; i < 5; ++i) {
        const int idx = tid + i*NT;                 // 5*128 = 640 = TQ exactly
        const int r = idx >> 6, q = idx & (W4_-1);
        const int h = h0 - 1 + r;
        const bool v = (h >= 0) && (h < H_);
        const float4* src = xc4 + (v ? (h*W4_ + q) : q);
        const int sz = v ? 16 : 0;
        const unsigned dst = sbase + (unsigned)(r*WP + 4 + 4*q)*4u;
        asm volatile("cp.async.cg.shared.global [%0], [%1], 16, %2;"
                     :: "r"(dst), "l"(src), "r"(sz));
    }
}

// 5 shifted operand pairs for one tile row, covering 4 pixels (2 f32x2 pairs)
struct RowP { u64 P0, P1, P2, P3, P4; };

__device__ __forceinline__ RowP load_row(const float* rb) {   // rb -> first data col of this thread
    RowP p;
    const float  L = rb[-1];
    const float4 M = *(const float4*)rb;            // LDS.128, 16B aligned
    const float  R = rb[4];
    p.P0 = pack2(L,   M.x); p.P1 = pack2(M.x, M.y); p.P2 = pack2(M.y, M.z);
    p.P3 = pack2(M.z, M.w); p.P4 = pack2(M.w, R);
    return p;
}

// accumulate one tile row into one output row's pair partials with weight row base b
#define ROW_ACC(r, b, oA, oB)                                             \
    oA = fma2((r).P0, wkp[b],   oA);                                      \
    oA = fma2((r).P1, wkp[b+1], oA);                                      \
    oA = fma2((r).P2, wkp[b+2], oA);                                      \
    oB = fma2((r).P2, wkp[b],   oB);                                      \
    oB = fma2((r).P3, wkp[b+1], oB);                                      \
    oB = fma2((r).P4, wkp[b+2], oB);

// row-sweep 3x3 conv over this thread's 4 output rows; 1 RowP live at a time.
// SINK(o, cA, cB) fires when output row o completes.
#define CONV_SWEEP(tb, wkp, SINK)                                         \
    {                                                                     \
        u64 oA[4] = {0,0,0,0}, oB[4] = {0,0,0,0};                         \
        _Pragma("unroll")                                                 \
        for (int tr = 0; tr < 6; ++tr) {                                  \
            RowP r = load_row((tb) + (4*ty + tr)*WP);                     \
            _Pragma("unroll")                                             \
            for (int o = 0; o < 4; ++o) {                                 \
                if (o >= tr - 2 && o <= tr) {                             \
                    ROW_ACC(r, 3*(tr - o), oA[o], oB[o]);                 \
                }                                                         \
            }                                                             \
            if (tr >= 2) { const int o = tr - 2; SINK(o, oA[o], oB[o]); } \
        }                                                                 \
    }

// zero halo columns (cols 3 and 260) of all TR rows in all 3 buffers
#define ZERO_HALOS(bufbase)                                               \
    if (tid < 3*TR*2) {                                                   \
        const int b = tid / (TR*2), rest = tid % (TR*2);                  \
        const int row = rest >> 1, col = (rest & 1) ? 260 : 3;            \
        (bufbase)[b*BUFF + row*WP + col] = 0.f;                           \
    }

// load the 9 x CPG_ weights as duplicated float2 (all 72 entries)
#define LOAD_WEIGHTS()                                                    \
    if (tid < 9*CPG_) {                                                   \
        const int j = tid / CPG_, cc = tid % CPG_;                        \
        const float w = wgt[j*C_ + g*CPG_ + cc];                          \
        wsm2[j][cc] = make_float2(w, w);                                  \
    }

// ---------------- Pass 1: depthwise conv + per-(n,g,chunk) sum / sumsq ----------------
__global__ __launch_bounds__(NT, 8) void k_pass1(const float* __restrict__ x,
                                                 const float* __restrict__ wgt) {
    __shared__ __align__(16) float buf[3*BUFF];
    __shared__ float2 wsm2[9][CPG_];
    __shared__ float  red[4], red2[4];

    const int bid   = blockIdx.x;
    const int chunk = bid % CHUNKS;
    const int g     = (bid / CHUNKS) % G_;
    const int n     = bid / (CHUNKS * G_);
    const int h0    = chunk * ROWS;
    const int tid   = threadIdx.x;
    const int tx    = tid & 63;                     // cols 4tx..4tx+3
    const int ty    = tid >> 6;                     // rows 4ty..4ty+3
    const int lane  = tid & 31, wid = tid >> 5;

    ZERO_HALOS(buf);
    LOAD_WEIGHTS();

    const unsigned sb0 = (unsigned)__cvta_generic_to_shared(&buf[0]);
    const float4* x4 = (const float4*)x;
    const size_t plane0 = (size_t)(n*C_ + g*CPG_) * HWQ;

    cpa_tile(sb0,                    x4 + plane0,       h0, tid); CP_COMMIT();
    cpa_tile(sb0 + (unsigned)BUFF*4, x4 + plane0 + HWQ, h0, tid); CP_COMMIT();

    u64 gsP = 0, gs2P = 0;
    int bsel = 0;
    for (int cc = 0; cc < CPG_; ++cc) {
        CP_WAIT1();
        __syncthreads();
        if (cc + 2 < CPG_) {
            const int nb = (bsel + 2 >= 3) ? bsel - 1 : bsel + 2;
            cpa_tile(sb0 + (unsigned)(nb*BUFF)*4, x4 + plane0 + (size_t)(cc+2)*HWQ, h0, tid);
        }
        CP_COMMIT();

        u64 wkp[9];
        #pragma unroll
        for (int j = 0; j < 9; ++j) wkp[j] = *(const u64*)&wsm2[j][cc];

        const float* tb = buf + bsel*BUFF + 4 + 4*tx;
        #define SINK1(o, cA, cB)                                          \
            gsP  = add2(gsP, add2(cA, cB));                               \
            gs2P = fma2(cA, cA, gs2P);                                    \
            gs2P = fma2(cB, cB, gs2P);
        CONV_SWEEP(tb, wkp, SINK1);
        #undef SINK1
        bsel = (bsel + 1 == 3) ? 0 : bsel + 1;
    }

    float a, b, gs, gs2;
    unpack2(gsP,  a, b); gs  = a + b;
    unpack2(gs2P, a, b); gs2 = a + b;
    #pragma unroll
    for (int off = 16; off; off >>= 1) {
        gs  += __shfl_down_sync(0xffffffffu, gs,  off);
        gs2 += __shfl_down_sync(0xffffffffu, gs2, off);
    }
    if (lane == 0) { red[wid] = gs; red2[wid] = gs2; }
    __syncthreads();
    if (tid == 0) {
        float s  = red[0] + red[1] + red[2] + red[3];
        float s2 = red2[0] + red2[1] + red2[2] + red2[3];
        const int idx = ((n*G_ + g)*CHUNKS + chunk)*2;
        g_part[idx]   = s;
        g_part[idx+1] = s2;
    }
}

// ---------------- Pass 2a: conv recompute + norm/act/residual + group exp-sum ----------------
__global__ __launch_bounds__(NT, 8) void k_pass2a(const float* __restrict__ x,
                                                  const float* __restrict__ wgt) {
    __shared__ __align__(16) float buf[3*BUFF];
    __shared__ float2 wsm2[9][CPG_];
    __shared__ float  s_stats[2];

    const int bid   = (gridDim.x - 1) - blockIdx.x;
    const int chunk = bid % CHUNKS;
    const int g     = (bid / CHUNKS) % G_;
    const int n     = bid / (CHUNKS * G_);
    const int h0    = chunk * ROWS;
    const int tid   = threadIdx.x;
    const int tx    = tid & 63;
    const int ty    = tid >> 6;

    ZERO_HALOS(buf);
    LOAD_WEIGHTS();
    // fold stats reduce: 32 chunk-partials for this (n,g), warp 3
    if (tid >= 96) {
        const int l = tid - 96;
        const int sg = (n*G_ + g)*CHUNKS;
        float s  = g_part[(sg + l)*2];
        float s2 = g_part[(sg + l)*2 + 1];
        #pragma unroll
        for (int off = 16; off; off >>= 1) {
            s  += __shfl_down_sync(0xffffffffu, s,  off);
            s2 += __shfl_down_sync(0xffffffffu, s2, off);
        }
        if (l == 0) {
            const float inv = 1.0f / (float)(CPG_*H_*W_);
            const float m = s * inv;
            const float v = s2 * inv - m*m;
            s_stats[0] = m;
            s_stats[1] = rsqrtf(v + EPS_);
        }
    }

    const unsigned sb0 = (unsigned)__cvta_generic_to_shared(&buf[0]);
    const float4* x4 = (const float4*)x;
    const size_t plane0 = (size_t)(n*C_ + g*CPG_) * HWQ;

    cpa_tile(sb0,                    x4 + plane0,       h0, tid); CP_COMMIT();
    cpa_tile(sb0 + (unsigned)BUFF*4, x4 + plane0 + HWQ, h0, tid); CP_COMMIT();

    u64 acc[8];                                     // 4 rows x {A,B}
    #pragma unroll
    for (int i = 0; i < 8; ++i) acc[i] = 0;

    const u64 threeP = pack2(3.0f, 3.0f);
    const u64 sixthP = pack2(1.0f/6.0f, 1.0f/6.0f);
    const u64 log2eP = pack2(1.4426950408889634f, 1.4426950408889634f);

    int bsel = 0;
    for (int cc = 0; cc < CPG_; ++cc) {
        CP_WAIT1();
        __syncthreads();                            // also publishes s_stats
        const float mean = s_stats[0];
        const float rstd = s_stats[1];
        const u64 rstdP = pack2(rstd, rstd);
        const u64 nmrP  = pack2(-mean*rstd, -mean*rstd);
        if (cc + 2 < CPG_) {
            const int nb = (bsel + 2 >= 3) ? bsel - 1 : bsel + 2;
            cpa_tile(sb0 + (unsigned)(nb*BUFF)*4, x4 + plane0 + (size_t)(cc+2)*HWQ, h0, tid);
        }
        CP_COMMIT();

        u64 wkp[9];
        #pragma unroll
        for (int j = 0; j < 9; ++j) wkp[j] = *(const u64*)&wsm2[j][cc];

        const float* tb = buf + bsel*BUFF + 4 + 4*tx;
        #define SINK2(o, cA, cB)                                          \
            {                                                             \
                u64 cv2[2] = { cA, cB };                                  \
                _Pragma("unroll")                                         \
                for (int h = 0; h < 2; ++h) {                             \
                    const u64 vP = fma2(cv2[h], rstdP, nmrP);             \
                    float v0, v1; unpack2(vP, v0, v1);                    \
                    const u64 tP = pack2(tanh_fast(v0), tanh_fast(v1));   \
                    const u64 xrP = fma2(mul2(tP, sixthP), add2(tP, threeP), cv2[h]); \
                    const u64 aP  = mul2(xrP, log2eP);                    \
                    float a0, a1; unpack2(aP, a0, a1);                    \
                    const u64 eP = pack2(ex2_fast(a0), ex2_fast(a1));     \
                    acc[(o)*2+h] = add2(acc[(o)*2+h], eP);                \
                }                                                         \
            }
        CONV_SWEEP(tb, wkp, SINK2);
        #undef SINK2
        bsel = (bsel + 1 == 3) ? 0 : bsel + 1;
    }

    float* es = g_esum + ((size_t)(n*G_ + g)*H_ + h0 + 4*ty)*W_ + 4*tx;
    #pragma unroll
    for (int rr = 0; rr < 4; ++rr) {
        float4 o;
        unpack2(acc[rr*2+0], o.x, o.y);
        unpack2(acc[rr*2+1], o.z, o.w);
        *(float4*)(es + rr*W_) = o;
    }
}

// ---------------- Pass 2b: combine groups, log, broadcast 8 channels/block ----------------
__global__ __launch_bounds__(256) void k_pass2b(float* __restrict__ out) {
    const int p   = blockIdx.x * 256 + threadIdx.x;
    const int n   = p >> 14;
    const int pix = p & (HWQ - 1);
    const int c0  = blockIdx.y * CHPB;

    const float4* e4 = (const float4*)g_esum;
    const size_t ebase = (size_t)n*G_*HWQ + pix;
    float4 s = __ldg(&e4[ebase]);
    #pragma unroll
    for (int g = 1; g < G_; ++g) {
        const float4 v = __ldg(&e4[ebase + (size_t)g*HWQ]);
        s.x += v.x; s.y += v.y; s.z += v.z; s.w += v.w;
    }
    float4 L;
    L.x = __logf(s.x); L.y = __logf(s.y); L.z = __logf(s.z); L.w = __logf(s.w);

    float4* o4 = (float4*)out;
    const size_t obase = (size_t)n*C_*HWQ + (size_t)c0*HWQ + pix;
    #pragma unroll
    for (int c = 0; c < CHPB; ++c) __stcs(&o4[obase + (size_t)c*HWQ], L);
}

extern "C" void kernel_launch(void* const* d_in, const int* in_sizes, int n_in,
                              void* d_out, int out_size) {
    const float* x   = (const float*)d_in[0];       // [8,64,256,256]
    const float* wgt = (const float*)d_in[1];       // [3,3,64]
    float* out = (float*)d_out;

    k_pass1 <<<N_*G_*CHUNKS, NT>>>(x, wgt);
    k_pass2a<<<N_*G_*CHUNKS, NT>>>(x, wgt);
    k_pass2b<<<dim3((N_*HWQ)/256, CSPLIT), 256>>>(out);
}

// round 12
// speedup vs baseline: 1.0439x; 1.0060x over previous
#include <cuda_runtime.h>
#include <cstdint>

#define N_   8
#define C_   64
#define H_   256
#define W_   256
#define G_   8
#define CPG_ 8               // channels per group
#define ROWS 8               // rows per block strip
#define TR   (ROWS+2)        // tile rows incl. halo
#define CHUNKS (H_/ROWS)     // 32
#define EPS_ 1e-5f
#define NT   128             // 64 col-groups x 2 row-groups
#define W4_  (W_/4)          // 64
#define TQ   (TR*W4_)        // 640 staging quads (= 5*NT exactly)
#define WP   264             // padded row width: col3 = L-halo, cols4..259 data, col260 = R-halo
#define BUFF (TR*WP)         // floats per tile buffer
#define HWQ  (H_*W_/4)
#define CSPLIT 4
#define CHPB (C_/CSPLIT)     // 16 channels per pass2b block

typedef unsigned long long u64;

// Static scratch (no runtime allocation)
__device__ float g_part[N_*G_*CHUNKS*2];
__device__ float g_esum[(size_t)N_*G_*H_*W_];      // per-(n,g) sum of exp

// ---- f32x2 packed helpers (sm_100+) ----
__device__ __forceinline__ u64 pack2(float lo, float hi) {
    u64 r; asm("mov.b64 %0,{%1,%2};" : "=l"(r) : "f"(lo), "f"(hi)); return r;
}
__device__ __forceinline__ void unpack2(u64 v, float& lo, float& hi) {
    asm("mov.b64 {%0,%1},%2;" : "=f"(lo), "=f"(hi) : "l"(v));
}
__device__ __forceinline__ u64 fma2(u64 a, u64 b, u64 c) {
    u64 d; asm("fma.rn.f32x2 %0,%1,%2,%3;" : "=l"(d) : "l"(a), "l"(b), "l"(c)); return d;
}
__device__ __forceinline__ u64 add2(u64 a, u64 b) {
    u64 d; asm("add.rn.f32x2 %0,%1,%2;" : "=l"(d) : "l"(a), "l"(b)); return d;
}
__device__ __forceinline__ u64 mul2(u64 a, u64 b) {
    u64 d; asm("mul.rn.f32x2 %0,%1,%2;" : "=l"(d) : "l"(a), "l"(b)); return d;
}
__device__ __forceinline__ float tanh_fast(float x) {
    float y; asm("tanh.approx.f32 %0,%1;" : "=f"(y) : "f"(x)); return y;
}
__device__ __forceinline__ float ex2_fast(float x) {
    float y; asm("ex2.approx.f32 %0,%1;" : "=f"(y) : "f"(x)); return y;
}

#define CP_COMMIT() asm volatile("cp.async.commit_group;")
#define CP_WAIT0()  asm volatile("cp.async.wait_group 0;")

// Stage one (TR x W_) channel tile gmem -> padded smem rows via cp.async.cg.
__device__ __forceinline__ void cpa_tile(unsigned sbase, const float4* __restrict__ xc4,
                                         int h0, int tid) {
    #pragma unroll
    for (int i = 0; i < 5; ++i) {
        const int idx = tid + i*NT;                 // 5*128 = 640 = TQ exactly
        const int r = idx >> 6, q = idx & (W4_-1);
        const int h = h0 - 1 + r;
        const bool v = (h >= 0) && (h < H_);
        const float4* src = xc4 + (v ? (h*W4_ + q) : q);
        const int sz = v ? 16 : 0;
        const unsigned dst = sbase + (unsigned)(r*WP + 4 + 4*q)*4u;
        asm volatile("cp.async.cg.shared.global [%0], [%1], 16, %2;"
                     :: "r"(dst), "l"(src), "r"(sz));
    }
}

// 5 shifted operand pairs for one tile row, covering 4 pixels (2 f32x2 pairs)
struct RowP { u64 P0, P1, P2, P3, P4; };

__device__ __forceinline__ RowP load_row(const float* rb) {   // rb -> first data col of this thread
    RowP p;
    const float  L = rb[-1];
    const float4 M = *(const float4*)rb;            // LDS.128, 16B aligned
    const float  R = rb[4];
    p.P0 = pack2(L,   M.x); p.P1 = pack2(M.x, M.y); p.P2 = pack2(M.y, M.z);
    p.P3 = pack2(M.z, M.w); p.P4 = pack2(M.w, R);
    return p;
}

// accumulate one tile row into one output row's pair partials with weight row base b
#define ROW_ACC(r, b, oA, oB)                                             \
    oA = fma2((r).P0, wkp[b],   oA);                                      \
    oA = fma2((r).P1, wkp[b+1], oA);                                      \
    oA = fma2((r).P2, wkp[b+2], oA);                                      \
    oB = fma2((r).P2, wkp[b],   oB);                                      \
    oB = fma2((r).P3, wkp[b+1], oB);                                      \
    oB = fma2((r).P4, wkp[b+2], oB);

// row-sweep 3x3 conv over this thread's 4 output rows; 1 RowP live at a time.
// SINK(o, cA, cB) fires when output row o completes.
#define CONV_SWEEP(tb, wkp, SINK)                                         \
    {                                                                     \
        u64 oA[4] = {0,0,0,0}, oB[4] = {0,0,0,0};                         \
        _Pragma("unroll")                                                 \
        for (int tr = 0; tr < 6; ++tr) {                                  \
            RowP r = load_row((tb) + (4*ty + tr)*WP);                     \
            _Pragma("unroll")                                             \
            for (int o = 0; o < 4; ++o) {                                 \
                if (o >= tr - 2 && o <= tr) {                             \
                    ROW_ACC(r, 3*(tr - o), oA[o], oB[o]);                 \
                }                                                         \
            }                                                             \
            if (tr >= 2) { const int o = tr - 2; SINK(o, oA[o], oB[o]); } \
        }                                                                 \
    }

// zero halo columns (cols 3 and 260) of all TR rows in both buffers
#define ZERO_HALOS(bufbase)                                               \
    if (tid < 2*TR*2) {                                                   \
        const int b = tid / (TR*2), rest = tid % (TR*2);                  \
        const int row = rest >> 1, col = (rest & 1) ? 260 : 3;            \
        (bufbase)[b*BUFF + row*WP + col] = 0.f;                           \
    }

// load the 9 x CPG_ weights as duplicated float2 (all 72 entries)
#define LOAD_WEIGHTS()                                                    \
    if (tid < 9*CPG_) {                                                   \
        const int j = tid / CPG_, cc = tid % CPG_;                        \
        const float w = wgt[j*C_ + g*CPG_ + cc];                          \
        wsm2[j][cc] = make_float2(w, w);                                  \
    }

// ---------------- Pass 1: depthwise conv + per-(n,g,chunk) sum / sumsq ----------------
__global__ __launch_bounds__(NT, 8) void k_pass1(const float* __restrict__ x,
                                                 const float* __restrict__ wgt) {
    __shared__ __align__(16) float buf[2*BUFF];     // 21.1 KB double buffer
    __shared__ float2 wsm2[9][CPG_];
    __shared__ float  red[4], red2[4];

    const int bid   = blockIdx.x;
    const int chunk = bid % CHUNKS;
    const int g     = (bid / CHUNKS) % G_;
    const int n     = bid / (CHUNKS * G_);
    const int h0    = chunk * ROWS;
    const int tid   = threadIdx.x;
    const int tx    = tid & 63;                     // cols 4tx..4tx+3
    const int ty    = tid >> 6;                     // rows 4ty..4ty+3
    const int lane  = tid & 31, wid = tid >> 5;

    ZERO_HALOS(buf);
    LOAD_WEIGHTS();

    const unsigned sb0 = (unsigned)__cvta_generic_to_shared(&buf[0]);
    const float4* x4 = (const float4*)x;
    const size_t plane0 = (size_t)(n*C_ + g*CPG_) * HWQ;

    cpa_tile(sb0, x4 + plane0, h0, tid); CP_COMMIT();

    u64 gsP = 0, gs2P = 0;
    int cur = 0;
    for (int cc = 0; cc < CPG_; ++cc) {
        CP_WAIT0();                                 // channel cc resident
        __syncthreads();                            // everyone done with the other buffer
        if (cc + 1 < CPG_) {
            cpa_tile(sb0 + (unsigned)((cur^1)*BUFF)*4u,
                     x4 + plane0 + (size_t)(cc+1)*HWQ, h0, tid);
            CP_COMMIT();
        }

        u64 wkp[9];
        #pragma unroll
        for (int j = 0; j < 9; ++j) wkp[j] = *(const u64*)&wsm2[j][cc];

        const float* tb = buf + cur*BUFF + 4 + 4*tx;
        #define SINK1(o, cA, cB)                                          \
            gsP  = add2(gsP, add2(cA, cB));                               \
            gs2P = fma2(cA, cA, gs2P);                                    \
            gs2P = fma2(cB, cB, gs2P);
        CONV_SWEEP(tb, wkp, SINK1);
        #undef SINK1
        cur ^= 1;
    }

    float a, b, gs, gs2;
    unpack2(gsP,  a, b); gs  = a + b;
    unpack2(gs2P, a, b); gs2 = a + b;
    #pragma unroll
    for (int off = 16; off; off >>= 1) {
        gs  += __shfl_down_sync(0xffffffffu, gs,  off);
        gs2 += __shfl_down_sync(0xffffffffu, gs2, off);
    }
    if (lane == 0) { red[wid] = gs; red2[wid] = gs2; }
    __syncthreads();
    if (tid == 0) {
        float s  = red[0] + red[1] + red[2] + red[3];
        float s2 = red2[0] + red2[1] + red2[2] + red2[3];
        const int idx = ((n*G_ + g)*CHUNKS + chunk)*2;
        g_part[idx]   = s;
        g_part[idx+1] = s2;
    }
}

// ---------------- Pass 2a: conv recompute + norm/act/residual + group exp-sum ----------------
__global__ __launch_bounds__(NT, 8) void k_pass2a(const float* __restrict__ x,
                                                  const float* __restrict__ wgt) {
    __shared__ __align__(16) float buf[2*BUFF];
    __shared__ float2 wsm2[9][CPG_];
    __shared__ float  s_stats[2];

    const int bid   = (gridDim.x - 1) - blockIdx.x;
    const int chunk = bid % CHUNKS;
    const int g     = (bid / CHUNKS) % G_;
    const int n     = bid / (CHUNKS * G_);
    const int h0    = chunk * ROWS;
    const int tid   = threadIdx.x;
    const int tx    = tid & 63;
    const int ty    = tid >> 6;

    ZERO_HALOS(buf);
    LOAD_WEIGHTS();
    // fold stats reduce: 32 chunk-partials for this (n,g), warp 3
    if (tid >= 96) {
        const int l = tid - 96;
        const int sg = (n*G_ + g)*CHUNKS;
        float s  = g_part[(sg + l)*2];
        float s2 = g_part[(sg + l)*2 + 1];
        #pragma unroll
        for (int off = 16; off; off >>= 1) {
            s  += __shfl_down_sync(0xffffffffu, s,  off);
            s2 += __shfl_down_sync(0xffffffffu, s2, off);
        }
        if (l == 0) {
            const float inv = 1.0f / (float)(CPG_*H_*W_);
            const float m = s * inv;
            const float v = s2 * inv - m*m;
            s_stats[0] = m;
            s_stats[1] = rsqrtf(v + EPS_);
        }
    }

    const unsigned sb0 = (unsigned)__cvta_generic_to_shared(&buf[0]);
    const float4* x4 = (const float4*)x;
    const size_t plane0 = (size_t)(n*C_ + g*CPG_) * HWQ;

    cpa_tile(sb0, x4 + plane0, h0, tid); CP_COMMIT();

    u64 acc[8];                                     // 4 rows x {A,B}
    #pragma unroll
    for (int i = 0; i < 8; ++i) acc[i] = 0;

    const u64 threeP = pack2(3.0f, 3.0f);
    const u64 sixthP = pack2(1.0f/6.0f, 1.0f/6.0f);
    const u64 log2eP = pack2(1.4426950408889634f, 1.4426950408889634f);

    int cur = 0;
    for (int cc = 0; cc < CPG_; ++cc) {
        CP_WAIT0();
        __syncthreads();                            // also publishes s_stats
        const float mean = s_stats[0];
        const float rstd = s_stats[1];
        const u64 rstdP = pack2(rstd, rstd);
        const u64 nmrP  = pack2(-mean*rstd, -mean*rstd);
        if (cc + 1 < CPG_) {
            cpa_tile(sb0 + (unsigned)((cur^1)*BUFF)*4u,
                     x4 + plane0 + (size_t)(cc+1)*HWQ, h0, tid);
            CP_COMMIT();
        }

        u64 wkp[9];
        #pragma unroll
        for (int j = 0; j < 9; ++j) wkp[j] = *(const u64*)&wsm2[j][cc];

        const float* tb = buf + cur*BUFF + 4 + 4*tx;
        #define SINK2(o, cA, cB)                                          \
            {                                                             \
                u64 cv2[2] = { cA, cB };                                  \
                _Pragma("unroll")                                         \
                for (int h = 0; h < 2; ++h) {                             \
                    const u64 vP = fma2(cv2[h], rstdP, nmrP);             \
                    float v0, v1; unpack2(vP, v0, v1);                    \
                    const u64 tP = pack2(tanh_fast(v0), tanh_fast(v1));   \
                    const u64 xrP = fma2(mul2(tP, sixthP), add2(tP, threeP), cv2[h]); \
                    const u64 aP  = mul2(xrP, log2eP);                    \
                    float a0, a1; unpack2(aP, a0, a1);                    \
                    const u64 eP = pack2(ex2_fast(a0), ex2_fast(a1));     \
                    acc[(o)*2+h] = add2(acc[(o)*2+h], eP);                \
                }                                                         \
            }
        CONV_SWEEP(tb, wkp, SINK2);
        #undef SINK2
        cur ^= 1;
    }

    float* es = g_esum + ((size_t)(n*G_ + g)*H_ + h0 + 4*ty)*W_ + 4*tx;
    #pragma unroll
    for (int rr = 0; rr < 4; ++rr) {
        float4 o;
        unpack2(acc[rr*2+0], o.x, o.y);
        unpack2(acc[rr*2+1], o.z, o.w);
        *(float4*)(es + rr*W_) = o;
    }
}

// ---------------- Pass 2b: combine groups, log, broadcast 16 channels/block ----------------
__global__ __launch_bounds__(256) void k_pass2b(float* __restrict__ out) {
    const int p   = blockIdx.x * 256 + threadIdx.x;
    const int n   = p >> 14;
    const int pix = p & (HWQ - 1);
    const int c0  = blockIdx.y * CHPB;

    const float4* e4 = (const float4*)g_esum;
    const size_t ebase = (size_t)n*G_*HWQ + pix;
    float4 s = __ldg(&e4[ebase]);
    #pragma unroll
    for (int g = 1; g < G_; ++g) {
        const float4 v = __ldg(&e4[ebase + (size_t)g*HWQ]);
        s.x += v.x; s.y += v.y; s.z += v.z; s.w += v.w;
    }
    float4 L;
    L.x = __logf(s.x); L.y = __logf(s.y); L.z = __logf(s.z); L.w = __logf(s.w);

    float4* o4 = (float4*)out;
    const size_t obase = (size_t)n*C_*HWQ + (size_t)c0*HWQ + pix;
    #pragma unroll
    for (int c = 0; c < CHPB; ++c) __stcs(&o4[obase + (size_t)c*HWQ], L);
}

extern "C" void kernel_launch(void* const* d_in, const int* in_sizes, int n_in,
                              void* d_out, int out_size) {
    const float* x   = (const float*)d_in[0];       // [8,64,256,256]
    const float* wgt = (const float*)d_in[1];       // [3,3,64]
    float* out = (float*)d_out;

    k_pass1 <<<N_*G_*CHUNKS, NT>>>(x, wgt);
    k_pass2a<<<N_*G_*CHUNKS, NT>>>(x, wgt);
    k_pass2b<<<dim3((N_*HWQ)/256, CSPLIT), 256>>>(out);
}